// round 1
// baseline (speedup 1.0000x reference)
#include <cuda_runtime.h>
#include <cuda_bf16.h>
#include <math.h>

#define N_S   8192
#define N_Q   16384
#define DIM   128
#define TOPK  32
#define NTILE 64            // 8192/128 tiles per dim

// ---------------- device scratch (module globals; no runtime allocation) ----
__device__ float g_xn[N_S * DIM];                 // normalized s_emb (4 MB)
__device__ float g_sim[(size_t)N_S * N_S];        // full sim matrix (268 MB)
__device__ float g_protoPart[64 * DIM];           // partial column sums
__device__ float g_V[2 * DIM];                    // V rows for 2 prototypes
__device__ float g_u[2 * DIM];                    // Wq^T @ K_p
__device__ float g_c[2];                          // bq . K_p

// ---------------- prototype partial sums ------------------------------------
__global__ void proto_part_kernel(const float* __restrict__ s) {
    int b = blockIdx.x;        // 64 blocks, each 128 rows
    int d = threadIdx.x;       // 128 threads
    const float* p = s + (size_t)b * 128 * DIM + d;
    float acc = 0.f;
#pragma unroll 8
    for (int r = 0; r < 128; r++) acc += p[(size_t)r * DIM];
    g_protoPart[b * DIM + d] = acc;
}

// ---------------- finish protos, compute K,V,u,c -----------------------------
__global__ void proto_finish_kernel(const float* __restrict__ Wq,
                                    const float* __restrict__ bq,
                                    const float* __restrict__ Wk,
                                    const float* __restrict__ bk,
                                    const float* __restrict__ Wv,
                                    const float* __restrict__ bv) {
    __shared__ float sp[2][DIM];   // proto: [0]=pos(second half), [1]=neg(first half)
    __shared__ float sk[2][DIM];   // K rows
    int d = threadIdx.x;           // 128 threads
    float neg = 0.f, pos = 0.f;
    for (int b = 0; b < 32; b++)  neg += g_protoPart[b * DIM + d];
    for (int b = 32; b < 64; b++) pos += g_protoPart[b * DIM + d];
    sp[0][d] = pos * (1.0f / 4096.0f);
    sp[1][d] = neg * (1.0f / 4096.0f);
    __syncthreads();

    float k0 = bk[d], k1 = bk[d], v0 = bv[d], v1 = bv[d];
    for (int e = 0; e < DIM; e++) {
        float wk = Wk[d * DIM + e];
        k0 = fmaf(sp[0][e], wk, k0);
        k1 = fmaf(sp[1][e], wk, k1);
        float wv = Wv[d * DIM + e];
        v0 = fmaf(sp[0][e], wv, v0);
        v1 = fmaf(sp[1][e], wv, v1);
    }
    g_V[d] = v0; g_V[DIM + d] = v1;
    sk[0][d] = k0; sk[1][d] = k1;
    __syncthreads();

    // u_p[d] = sum_e Wq[e, d] * K_p[e]
    float u0 = 0.f, u1 = 0.f;
    for (int e = 0; e < DIM; e++) {
        float wq = Wq[e * DIM + d];
        u0 = fmaf(wq, sk[0][e], u0);
        u1 = fmaf(wq, sk[1][e], u1);
    }
    g_u[d] = u0; g_u[DIM + d] = u1;
    if (d < 2) {
        float c = 0.f;
        for (int e = 0; e < DIM; e++) c = fmaf(bq[e], sk[d][e], c);
        g_c[d] = c;
    }
}

// ---------------- row normalization ------------------------------------------
__global__ void __launch_bounds__(256) norm_kernel(const float* __restrict__ s) {
    int w = (blockIdx.x * blockDim.x + threadIdx.x) >> 5;
    int lane = threadIdx.x & 31;
    if (w >= N_S) return;
    float4 x = *(const float4*)(s + (size_t)w * DIM + lane * 4);
    float ss = x.x * x.x + x.y * x.y + x.z * x.z + x.w * x.w;
#pragma unroll
    for (int o = 16; o; o >>= 1) ss += __shfl_xor_sync(0xffffffffu, ss, o);
    float n = sqrtf(ss);
    float4 y;
    y.x = x.x / n; y.y = x.y / n; y.z = x.z / n; y.w = x.w / n;
    *(float4*)(g_xn + (size_t)w * DIM + lane * 4) = y;
}

// ---------------- sim GEMM: C = Xn Xn^T, symmetric, 128x128 CTA tiles --------
__global__ void __launch_bounds__(256) sim_gemm_kernel() {
    extern __shared__ float smem[];
    float* As = smem;            // As[k][m], 128x128
    float* Bs = smem + 128 * 128;

    // map linear block id -> upper-tri tile (br <= bc)
    int t = blockIdx.x;
    int br = 0, rem = t;
    while (rem >= (NTILE - br)) { rem -= (NTILE - br); br++; }
    int bc = br + rem;

    int tid = threadIdx.x;
    int m = tid & 127;
    int half = tid >> 7;                 // 0/1
    const float* ga = g_xn + (size_t)(br * 128 + m) * DIM;
    const float* gb = g_xn + (size_t)(bc * 128 + m) * DIM;
#pragma unroll
    for (int i = 0; i < 16; i++) {
        int v = half * 16 + i;           // float4 index 0..31 over K
        float4 a = *(const float4*)(ga + v * 4);
        As[(v * 4 + 0) * 128 + m] = a.x;
        As[(v * 4 + 1) * 128 + m] = a.y;
        As[(v * 4 + 2) * 128 + m] = a.z;
        As[(v * 4 + 3) * 128 + m] = a.w;
        float4 b = *(const float4*)(gb + v * 4);
        Bs[(v * 4 + 0) * 128 + m] = b.x;
        Bs[(v * 4 + 1) * 128 + m] = b.y;
        Bs[(v * 4 + 2) * 128 + m] = b.z;
        Bs[(v * 4 + 3) * 128 + m] = b.w;
    }
    __syncthreads();

    int ty = tid >> 4;                   // 0..15 -> output rows ty*8..
    int tx = tid & 15;                   // 0..15 -> output cols tx*8..
    const float* ap = As + ty * 8;
    const float* bp = Bs + tx * 8;

    float acc[8][8];
#pragma unroll
    for (int r = 0; r < 8; r++)
#pragma unroll
        for (int c = 0; c < 8; c++) acc[r][c] = 0.f;

#pragma unroll 4
    for (int k = 0; k < 128; k++) {
        float4 a0 = *(const float4*)(ap + k * 128);
        float4 a1 = *(const float4*)(ap + k * 128 + 4);
        float4 b0 = *(const float4*)(bp + k * 128);
        float4 b1 = *(const float4*)(bp + k * 128 + 4);
        float a[8] = {a0.x, a0.y, a0.z, a0.w, a1.x, a1.y, a1.z, a1.w};
        float b[8] = {b0.x, b0.y, b0.z, b0.w, b1.x, b1.y, b1.z, b1.w};
#pragma unroll
        for (int r = 0; r < 8; r++)
#pragma unroll
            for (int c = 0; c < 8; c++)
                acc[r][c] = fmaf(a[r], b[c], acc[r][c]);
    }

    int row0 = br * 128 + ty * 8;
    int col0 = bc * 128 + tx * 8;
#pragma unroll
    for (int r = 0; r < 8; r++) {
        float4 p0 = make_float4(acc[r][0], acc[r][1], acc[r][2], acc[r][3]);
        float4 p1 = make_float4(acc[r][4], acc[r][5], acc[r][6], acc[r][7]);
        *(float4*)(g_sim + (size_t)(row0 + r) * N_S + col0) = p0;
        *(float4*)(g_sim + (size_t)(row0 + r) * N_S + col0 + 4) = p1;
    }
    if (br != bc) {
#pragma unroll
        for (int cc = 0; cc < 8; cc++) {
            float4 q0 = make_float4(acc[0][cc], acc[1][cc], acc[2][cc], acc[3][cc]);
            float4 q1 = make_float4(acc[4][cc], acc[5][cc], acc[6][cc], acc[7][cc]);
            *(float4*)(g_sim + (size_t)(col0 + cc) * N_S + row0) = q0;
            *(float4*)(g_sim + (size_t)(col0 + cc) * N_S + row0 + 4) = q1;
        }
    }
}

// ---------------- streaming top-32 + aggregation ------------------------------
// key: larger (value, smaller index) wins; eviction target = min value, ties ->
// larger index evicted (matches jax.lax.top_k stable smallest-index tie-break
// when streaming candidates in ascending index order with strict '>' insert).
__device__ __forceinline__ unsigned long long topk_key(float v, int i) {
    unsigned u = __float_as_uint(v);
    u = (u & 0x80000000u) ? ~u : (u | 0x80000000u);
    return (((unsigned long long)u) << 32) | (unsigned)(0xFFFFFFFFu - (unsigned)i);
}
__device__ __forceinline__ float topk_key_val(unsigned long long k) {
    unsigned u = (unsigned)(k >> 32);
    u = (u & 0x80000000u) ? (u ^ 0x80000000u) : ~u;
    return __uint_as_float(u);
}

__global__ void __launch_bounds__(256) topk_agg_kernel(const float* __restrict__ s_emb,
                                                       const float* __restrict__ alphaP,
                                                       float* __restrict__ out_s) {
    int w = (blockIdx.x * blockDim.x + threadIdx.x) >> 5;
    int lane = threadIdx.x & 31;
    if (w >= N_S) return;
    const float* srow = g_sim + (size_t)w * N_S;

    float bv = -2.0f;            // sims are in [-1,1] -> safe sentinel
    int   bi = -1;
    unsigned long long curKey = topk_key(bv, bi);
    float curMin = -2.0f;

    for (int base = 0; base < N_S; base += 32) {
        float v = srow[base + lane];
        unsigned mask = __ballot_sync(0xffffffffu, v > curMin);
        while (mask) {
            int l = __ffs(mask) - 1;
            mask &= mask - 1;
            float vl = __shfl_sync(0xffffffffu, v, l);
            if (vl > curMin) {
                unsigned long long myKey = topk_key(bv, bi);
                unsigned own = __ballot_sync(0xffffffffu, myKey == curKey);
                if (lane == __ffs(own) - 1) { bv = vl; bi = base + l; }
                unsigned long long k = topk_key(bv, bi);
#pragma unroll
                for (int o = 16; o; o >>= 1) {
                    unsigned long long t = __shfl_xor_sync(0xffffffffu, k, o);
                    if (t < k) k = t;
                }
                curKey = k;
                curMin = topk_key_val(k);
            }
        }
    }

    // aggregate: sum of the 32 selected s_emb rows
    float4 acc = make_float4(0.f, 0.f, 0.f, 0.f);
#pragma unroll 4
    for (int t = 0; t < 32; t++) {
        int idx = __shfl_sync(0xffffffffu, bi, t);
        float4 r = *(const float4*)(s_emb + (size_t)idx * DIM + lane * 4);
        acc.x += r.x; acc.y += r.y; acc.z += r.z; acc.w += r.w;
    }
    float al = *alphaP;
    float4 x = *(const float4*)(s_emb + (size_t)w * DIM + lane * 4);
    float4 o = make_float4(fmaf(al, acc.x, x.x), fmaf(al, acc.y, x.y),
                           fmaf(al, acc.z, x.z), fmaf(al, acc.w, x.w));
    *(float4*)(out_s + (size_t)w * DIM + lane * 4) = o;
}

// ---------------- query path ---------------------------------------------------
__global__ void __launch_bounds__(256) query_kernel(const float* __restrict__ q,
                                                    const float* __restrict__ alphaP,
                                                    float* __restrict__ outQ) {
    const float SCALEF = 11.313708498984760390413509793678f; // sqrt(128)
    int w = (blockIdx.x * blockDim.x + threadIdx.x) >> 5;
    int lane = threadIdx.x & 31;
    if (w >= N_Q) return;
    float4 x = *(const float4*)(q + (size_t)w * DIM + lane * 4);
    float4 u0 = *(const float4*)(g_u + lane * 4);
    float4 u1 = *(const float4*)(g_u + DIM + lane * 4);
    float d0 = x.x * u0.x + x.y * u0.y + x.z * u0.z + x.w * u0.w;
    float d1 = x.x * u1.x + x.y * u1.y + x.z * u1.z + x.w * u1.w;
#pragma unroll
    for (int o = 16; o; o >>= 1) {
        d0 += __shfl_xor_sync(0xffffffffu, d0, o);
        d1 += __shfl_xor_sync(0xffffffffu, d1, o);
    }
    float l0 = (d0 + g_c[0]) / SCALEF;
    float l1 = (d1 + g_c[1]) / SCALEF;
    float m  = fmaxf(l0, l1);
    float e0 = expf(l0 - m), e1 = expf(l1 - m);
    float inv = 1.0f / (e0 + e1);
    float a0 = e0 * inv, a1 = e1 * inv;
    float al = *alphaP;
    float4 v0 = *(const float4*)(g_V + lane * 4);
    float4 v1 = *(const float4*)(g_V + DIM + lane * 4);
    float4 o;
    o.x = fmaf(al, a0 * v0.x + a1 * v1.x, x.x);
    o.y = fmaf(al, a0 * v0.y + a1 * v1.y, x.y);
    o.z = fmaf(al, a0 * v0.z + a1 * v1.z, x.z);
    o.w = fmaf(al, a0 * v0.w + a1 * v1.w, x.w);
    *(float4*)(outQ + (size_t)w * DIM + lane * 4) = o;
}

// ---------------- launch ---------------------------------------------------------
extern "C" void kernel_launch(void* const* d_in, const int* in_sizes, int n_in,
                              void* d_out, int out_size) {
    const float* s_emb = (const float*)d_in[0];
    const float* q_emb = (const float*)d_in[1];
    const float* Wq = (const float*)d_in[2];
    const float* bq = (const float*)d_in[3];
    const float* Wk = (const float*)d_in[4];
    const float* bk = (const float*)d_in[5];
    const float* Wv = (const float*)d_in[6];
    const float* bv = (const float*)d_in[7];
    const float* alpha_msg  = (const float*)d_in[8];
    const float* alpha_attn = (const float*)d_in[9];
    float* out = (float*)d_out;

    // 128 KB dynamic smem for the GEMM (idempotent; immediate API, not captured)
    cudaFuncSetAttribute(sim_gemm_kernel,
                         cudaFuncAttributeMaxDynamicSharedMemorySize, 131072);

    proto_part_kernel<<<64, 128>>>(s_emb);
    proto_finish_kernel<<<1, 128>>>(Wq, bq, Wk, bk, Wv, bv);
    norm_kernel<<<N_S / 8, 256>>>(s_emb);

    int triBlocks = NTILE * (NTILE + 1) / 2;   // 2080
    sim_gemm_kernel<<<triBlocks, 256, 131072>>>();

    topk_agg_kernel<<<N_S / 8, 256>>>(s_emb, alpha_msg, out);
    query_kernel<<<N_Q / 8, 256>>>(q_emb, alpha_attn, out + (size_t)N_S * DIM);
}

// round 2
// speedup vs baseline: 1.1748x; 1.1748x over previous
#include <cuda_runtime.h>
#include <cuda_bf16.h>
#include <math.h>

#define N_S   8192
#define N_Q   16384
#define DIM   128
#define TOPK  32
#define NTILE 64            // 8192/128 tiles per dim

// ---------------- device scratch (module globals; no runtime allocation) ----
__device__ float g_xn[N_S * DIM];                 // normalized s_emb (4 MB)
__device__ float g_sim[(size_t)N_S * N_S];        // full sim matrix (268 MB)
__device__ float g_protoPart[64 * DIM];           // partial column sums
__device__ float g_V[2 * DIM];                    // V rows for 2 prototypes
__device__ float g_u[2 * DIM];                    // Wq^T @ K_p
__device__ float g_c[2];                          // bq . K_p

// ---------------- prototype partial sums ------------------------------------
__global__ void proto_part_kernel(const float* __restrict__ s) {
    int b = blockIdx.x;        // 64 blocks, each 128 rows
    int d = threadIdx.x;       // 128 threads
    const float* p = s + (size_t)b * 128 * DIM + d;
    float acc = 0.f;
#pragma unroll 8
    for (int r = 0; r < 128; r++) acc += p[(size_t)r * DIM];
    g_protoPart[b * DIM + d] = acc;
}

// ---------------- finish protos, compute K,V,u,c (coalesced rewrite) ---------
__global__ void __launch_bounds__(256) proto_finish_kernel(
        const float* __restrict__ Wq, const float* __restrict__ bq,
        const float* __restrict__ Wk, const float* __restrict__ bk,
        const float* __restrict__ Wv, const float* __restrict__ bv) {
    __shared__ float sp[2][DIM];   // proto: [0]=pos(second half), [1]=neg(first half)
    __shared__ float sk[2][DIM];   // K rows
    int tid  = threadIdx.x;
    int lane = tid & 31;
    int warp = tid >> 5;           // 8 warps

    if (tid < 128) {
        int d = tid;
        float neg = 0.f, pos = 0.f;
        for (int b = 0; b < 32; b++)  neg += g_protoPart[b * DIM + d];
        for (int b = 32; b < 64; b++) pos += g_protoPart[b * DIM + d];
        sp[0][d] = pos * (1.0f / 4096.0f);
        sp[1][d] = neg * (1.0f / 4096.0f);
    }
    __syncthreads();

    float4 s0 = ((const float4*)sp[0])[lane];
    float4 s1 = ((const float4*)sp[1])[lane];
    // 256 row-dot tasks: t<128 -> Wk row t (K), else Wv row t-128 (V)
    for (int t = warp; t < 256; t += 8) {
        const float* Wrow = (t < 128) ? (Wk + (size_t)t * DIM)
                                      : (Wv + (size_t)(t - 128) * DIM);
        float4 w = ((const float4*)Wrow)[lane];
        float d0 = w.x * s0.x + w.y * s0.y + w.z * s0.z + w.w * s0.w;
        float d1 = w.x * s1.x + w.y * s1.y + w.z * s1.z + w.w * s1.w;
#pragma unroll
        for (int o = 16; o; o >>= 1) {
            d0 += __shfl_xor_sync(0xffffffffu, d0, o);
            d1 += __shfl_xor_sync(0xffffffffu, d1, o);
        }
        if (lane == 0) {
            if (t < 128) { sk[0][t] = d0 + bk[t]; sk[1][t] = d1 + bk[t]; }
            else { g_V[t - 128] = d0 + bv[t - 128]; g_V[DIM + t - 128] = d1 + bv[t - 128]; }
        }
    }
    __syncthreads();

    if (tid < 128) {
        int d = tid;
        float u0 = 0.f, u1 = 0.f;
#pragma unroll 8
        for (int e = 0; e < DIM; e++) {
            float wq = Wq[(size_t)e * DIM + d];   // coalesced over d
            u0 = fmaf(wq, sk[0][e], u0);
            u1 = fmaf(wq, sk[1][e], u1);
        }
        g_u[d] = u0; g_u[DIM + d] = u1;
    }
    if (warp < 2) {
        float4 b4 = ((const float4*)bq)[lane];
        float4 k4 = ((const float4*)sk[warp])[lane];
        float c = b4.x * k4.x + b4.y * k4.y + b4.z * k4.z + b4.w * k4.w;
#pragma unroll
        for (int o = 16; o; o >>= 1) c += __shfl_xor_sync(0xffffffffu, c, o);
        if (lane == 0) g_c[warp] = c;
    }
}

// ---------------- row normalization ------------------------------------------
__global__ void __launch_bounds__(256) norm_kernel(const float* __restrict__ s) {
    int w = (blockIdx.x * blockDim.x + threadIdx.x) >> 5;
    int lane = threadIdx.x & 31;
    if (w >= N_S) return;
    float4 x = *(const float4*)(s + (size_t)w * DIM + lane * 4);
    float ss = x.x * x.x + x.y * x.y + x.z * x.z + x.w * x.w;
#pragma unroll
    for (int o = 16; o; o >>= 1) ss += __shfl_xor_sync(0xffffffffu, ss, o);
    float n = sqrtf(ss);
    float4 y;
    y.x = x.x / n; y.y = x.y / n; y.z = x.z / n; y.w = x.w / n;
    *(float4*)(g_xn + (size_t)w * DIM + lane * 4) = y;
}

// ---------------- sim GEMM: C = Xn Xn^T, symmetric, 128x128 CTA tiles --------
// K split into two 64-wide passes so smem = 64KB -> 2 CTAs/SM.
__global__ void __launch_bounds__(256, 2) sim_gemm_kernel() {
    extern __shared__ float smem[];
    float* As = smem;                 // As[kk][m], 64 x 128
    float* Bs = smem + 64 * 128;

    // map linear block id -> upper-tri tile (br <= bc)
    int t = blockIdx.x;
    int br = 0, rem = t;
    while (rem >= (NTILE - br)) { rem -= (NTILE - br); br++; }
    int bc = br + rem;

    int tid = threadIdx.x;
    int m = tid & 127;
    int half = tid >> 7;                 // 0/1
    const float4* ga = (const float4*)(g_xn + (size_t)(br * 128 + m) * DIM);
    const float4* gb = (const float4*)(g_xn + (size_t)(bc * 128 + m) * DIM);

    int ty = tid >> 4;                   // 0..15 -> output rows ty*8..
    int tx = tid & 15;                   // 0..15 -> output cols tx*8..
    const float* ap = As + ty * 8;
    const float* bp = Bs + tx * 8;

    float acc[8][8];
#pragma unroll
    for (int r = 0; r < 8; r++)
#pragma unroll
        for (int c = 0; c < 8; c++) acc[r][c] = 0.f;

#pragma unroll
    for (int kb = 0; kb < 2; kb++) {     // two 64-k passes
        if (kb) __syncthreads();         // protect smem reuse
#pragma unroll
        for (int i = 0; i < 8; i++) {
            int v = kb * 16 + half * 8 + i;      // global float4 k-index
            int kk = (v * 4) - kb * 64;          // local k base (0..60)
            float4 a = ga[v];
            As[(kk + 0) * 128 + m] = a.x;
            As[(kk + 1) * 128 + m] = a.y;
            As[(kk + 2) * 128 + m] = a.z;
            As[(kk + 3) * 128 + m] = a.w;
            float4 b = gb[v];
            Bs[(kk + 0) * 128 + m] = b.x;
            Bs[(kk + 1) * 128 + m] = b.y;
            Bs[(kk + 2) * 128 + m] = b.z;
            Bs[(kk + 3) * 128 + m] = b.w;
        }
        __syncthreads();

#pragma unroll 4
        for (int k = 0; k < 64; k++) {
            float4 a0 = *(const float4*)(ap + k * 128);
            float4 a1 = *(const float4*)(ap + k * 128 + 4);
            float4 b0 = *(const float4*)(bp + k * 128);
            float4 b1 = *(const float4*)(bp + k * 128 + 4);
            float a[8] = {a0.x, a0.y, a0.z, a0.w, a1.x, a1.y, a1.z, a1.w};
            float b[8] = {b0.x, b0.y, b0.z, b0.w, b1.x, b1.y, b1.z, b1.w};
#pragma unroll
            for (int r = 0; r < 8; r++)
#pragma unroll
                for (int c = 0; c < 8; c++)
                    acc[r][c] = fmaf(a[r], b[c], acc[r][c]);
        }
    }

    int row0 = br * 128 + ty * 8;
    int col0 = bc * 128 + tx * 8;
#pragma unroll
    for (int r = 0; r < 8; r++) {
        float4 p0 = make_float4(acc[r][0], acc[r][1], acc[r][2], acc[r][3]);
        float4 p1 = make_float4(acc[r][4], acc[r][5], acc[r][6], acc[r][7]);
        *(float4*)(g_sim + (size_t)(row0 + r) * N_S + col0) = p0;
        *(float4*)(g_sim + (size_t)(row0 + r) * N_S + col0 + 4) = p1;
    }
    if (br != bc) {
#pragma unroll
        for (int cc = 0; cc < 8; cc++) {
            float4 q0 = make_float4(acc[0][cc], acc[1][cc], acc[2][cc], acc[3][cc]);
            float4 q1 = make_float4(acc[4][cc], acc[5][cc], acc[6][cc], acc[7][cc]);
            *(float4*)(g_sim + (size_t)(col0 + cc) * N_S + row0) = q0;
            *(float4*)(g_sim + (size_t)(col0 + cc) * N_S + row0 + 4) = q1;
        }
    }
}

// ---------------- streaming top-32 + aggregation (redux.sync inserts) --------
// Semantics identical to R1 (which passed): stream ascending index, insert iff
// v > curMin (strict), evict slot with (min value, largest index among mins).
__device__ __forceinline__ unsigned ordf(float v) {
    unsigned u = __float_as_uint(v);
    return (u & 0x80000000u) ? ~u : (u | 0x80000000u);
}
__device__ __forceinline__ float unordf(unsigned u) {
    u = (u & 0x80000000u) ? (u ^ 0x80000000u) : ~u;
    return __uint_as_float(u);
}

__global__ void __launch_bounds__(256) topk_agg_kernel(const float* __restrict__ s_emb,
                                                       const float* __restrict__ alphaP,
                                                       float* __restrict__ out_s) {
    const unsigned FULL = 0xffffffffu;
    int w = (blockIdx.x * blockDim.x + threadIdx.x) >> 5;
    int lane = threadIdx.x & 31;
    if (w >= N_S) return;
    const float* srow = g_sim + (size_t)w * N_S;

    float bv = -2.0f;              // sims in [-1,1] -> safe sentinel
    int   bi = -1 - lane;          // distinct sentinel indices (evict order defined)
    float curMin = -2.0f;

    for (int base = 0; base < N_S; base += 32) {
        float v = srow[base + lane];
        unsigned mask = __ballot_sync(FULL, v > curMin);
        while (mask) {
            int l = __ffs(mask) - 1;
            mask &= mask - 1;
            float vl = __shfl_sync(FULL, v, l);
            if (vl > curMin) {     // recheck: curMin may have risen
                unsigned mo = ordf(bv);
                unsigned mn = __reduce_min_sync(FULL, mo);
                int evict = __reduce_max_sync(FULL, (mo == mn) ? bi : (int)0x80000000);
                if (bi == evict) { bv = vl; bi = base + l; }
                curMin = unordf(__reduce_min_sync(FULL, ordf(bv)));
            }
        }
    }

    // aggregate: sum of the 32 selected s_emb rows
    float4 acc = make_float4(0.f, 0.f, 0.f, 0.f);
#pragma unroll 4
    for (int t = 0; t < 32; t++) {
        int idx = __shfl_sync(FULL, bi, t);
        float4 r = *(const float4*)(s_emb + (size_t)idx * DIM + lane * 4);
        acc.x += r.x; acc.y += r.y; acc.z += r.z; acc.w += r.w;
    }
    float al = *alphaP;
    float4 x = *(const float4*)(s_emb + (size_t)w * DIM + lane * 4);
    float4 o = make_float4(fmaf(al, acc.x, x.x), fmaf(al, acc.y, x.y),
                           fmaf(al, acc.z, x.z), fmaf(al, acc.w, x.w));
    *(float4*)(out_s + (size_t)w * DIM + lane * 4) = o;
}

// ---------------- query path ---------------------------------------------------
__global__ void __launch_bounds__(256) query_kernel(const float* __restrict__ q,
                                                    const float* __restrict__ alphaP,
                                                    float* __restrict__ outQ) {
    const float SCALEF = 11.313708498984760390413509793678f; // sqrt(128)
    int w = (blockIdx.x * blockDim.x + threadIdx.x) >> 5;
    int lane = threadIdx.x & 31;
    if (w >= N_Q) return;
    float4 x = *(const float4*)(q + (size_t)w * DIM + lane * 4);
    float4 u0 = *(const float4*)(g_u + lane * 4);
    float4 u1 = *(const float4*)(g_u + DIM + lane * 4);
    float d0 = x.x * u0.x + x.y * u0.y + x.z * u0.z + x.w * u0.w;
    float d1 = x.x * u1.x + x.y * u1.y + x.z * u1.z + x.w * u1.w;
#pragma unroll
    for (int o = 16; o; o >>= 1) {
        d0 += __shfl_xor_sync(0xffffffffu, d0, o);
        d1 += __shfl_xor_sync(0xffffffffu, d1, o);
    }
    float l0 = (d0 + g_c[0]) / SCALEF;
    float l1 = (d1 + g_c[1]) / SCALEF;
    float m  = fmaxf(l0, l1);
    float e0 = expf(l0 - m), e1 = expf(l1 - m);
    float inv = 1.0f / (e0 + e1);
    float a0 = e0 * inv, a1 = e1 * inv;
    float al = *alphaP;
    float4 v0 = *(const float4*)(g_V + lane * 4);
    float4 v1 = *(const float4*)(g_V + DIM + lane * 4);
    float4 o;
    o.x = fmaf(al, a0 * v0.x + a1 * v1.x, x.x);
    o.y = fmaf(al, a0 * v0.y + a1 * v1.y, x.y);
    o.z = fmaf(al, a0 * v0.z + a1 * v1.z, x.z);
    o.w = fmaf(al, a0 * v0.w + a1 * v1.w, x.w);
    *(float4*)(outQ + (size_t)w * DIM + lane * 4) = o;
}

// ---------------- launch ---------------------------------------------------------
extern "C" void kernel_launch(void* const* d_in, const int* in_sizes, int n_in,
                              void* d_out, int out_size) {
    const float* s_emb = (const float*)d_in[0];
    const float* q_emb = (const float*)d_in[1];
    const float* Wq = (const float*)d_in[2];
    const float* bq = (const float*)d_in[3];
    const float* Wk = (const float*)d_in[4];
    const float* bk = (const float*)d_in[5];
    const float* Wv = (const float*)d_in[6];
    const float* bv = (const float*)d_in[7];
    const float* alpha_msg  = (const float*)d_in[8];
    const float* alpha_attn = (const float*)d_in[9];
    float* out = (float*)d_out;

    // 64 KB dynamic smem for the GEMM (idempotent; immediate API, not captured)
    cudaFuncSetAttribute(sim_gemm_kernel,
                         cudaFuncAttributeMaxDynamicSharedMemorySize, 65536);

    proto_part_kernel<<<64, 128>>>(s_emb);
    proto_finish_kernel<<<1, 256>>>(Wq, bq, Wk, bk, Wv, bv);
    norm_kernel<<<N_S / 8, 256>>>(s_emb);

    int triBlocks = NTILE * (NTILE + 1) / 2;   // 2080
    sim_gemm_kernel<<<triBlocks, 256, 65536>>>();

    topk_agg_kernel<<<N_S / 8, 256>>>(s_emb, alpha_msg, out);
    query_kernel<<<N_Q / 8, 256>>>(q_emb, alpha_attn, out + (size_t)N_S * DIM);
}